// round 1
// baseline (speedup 1.0000x reference)
#include <cuda_runtime.h>
#include <cuda_bf16.h>

// ---------------- problem constants ----------------
#define N_SRC0 300000
#define NDST0  100000
#define NDST1  20000
#define NDST2  4096
#define NE0    1000000
#define NE1    300000
#define NE2    61440
#define D_IN   128
#define D_H    256
#define D_OUT  47

// ---------------- scratch (device globals: allocation-free) ----------------
__device__ float g_agg0[(size_t)NDST0 * D_IN];   // 51.2 MB
__device__ float g_deg0[NDST0];
__device__ float g_h1[(size_t)NDST0 * D_H];      // 102.4 MB
__device__ float g_agg1[(size_t)NDST1 * D_H];    // 20.5 MB
__device__ float g_deg1[NDST1];
__device__ float g_h2[(size_t)NDST1 * D_H];      // 20.5 MB
__device__ float g_agg2[(size_t)NDST2 * D_H];    // 4.2 MB
__device__ float g_deg2[NDST2];

// ---------------- utility kernels ----------------
__global__ void fill0_kernel(float4* __restrict__ p, long long n4) {
    long long i = (long long)blockIdx.x * blockDim.x + threadIdx.x;
    long long stride = (long long)gridDim.x * blockDim.x;
    float4 z = make_float4(0.f, 0.f, 0.f, 0.f);
    for (; i < n4; i += stride) p[i] = z;
}

__global__ void invdeg_kernel(float* __restrict__ deg, int n) {
    int i = blockIdx.x * blockDim.x + threadIdx.x;
    if (i < n) deg[i] = 1.0f / fmaxf(deg[i], 1.0f);
}

// ---------------- edge scatter: agg[dst] += feat[src], deg[dst] += 1 ----------------
// One thread handles one float4 chunk of one edge. Vectorized global reduction
// (red.global.add.v4.f32, sm_90+) to quarter the L2 atomic op count.
__global__ void scatter_kernel(const float* __restrict__ feat,
                               const int* __restrict__ src,
                               const int* __restrict__ dst,
                               float* __restrict__ agg,
                               float* __restrict__ deg,
                               int E, int shift /* log2(d/4) */) {
    const int d4 = 1 << shift;
    const long long total = (long long)E << shift;
    const long long stride = (long long)gridDim.x * blockDim.x;
    for (long long i = (long long)blockIdx.x * blockDim.x + threadIdx.x;
         i < total; i += stride) {
        int e = (int)(i >> shift);
        int c = (int)(i & (d4 - 1));
        int s  = src[e];
        int dt = dst[e];
        float4 v = reinterpret_cast<const float4*>(feat)[(long long)s * d4 + c];
        float* p = agg + (((long long)dt << shift) + c) * 4;
        asm volatile("red.global.add.v4.f32 [%0], {%1,%2,%3,%4};"
                     :: "l"(p), "f"(v.x), "f"(v.y), "f"(v.z), "f"(v.w)
                     : "memory");
        if (c == 0) atomicAdd(deg + dt, 1.0f);
    }
}

// ---------------- fused SAGE GEMM ----------------
// out[m,n] = act( sum_k Adst[m,k]*Ws[k,n] + (Agg[m,k]*invdeg[m])*Wn[k,n] + b[n] )
// Implemented as a single GEMM over K' = 2K where tiles with k' >= K read the
// neighbor half. BM=128, BN=64, BK=16, 256 threads, 8x4 accum per thread.
#define BM 128
#define BN 64
#define BK 16

__global__ __launch_bounds__(256) void sage_gemm_kernel(
    const float* __restrict__ Adst, const float* __restrict__ Agg,
    const float* __restrict__ invdeg,
    const float* __restrict__ Ws, const float* __restrict__ Wn,
    const float* __restrict__ bias, float* __restrict__ out,
    int M, int N, int K, int do_relu)
{
    __shared__ float As[BM][BK + 1];
    __shared__ float Bs[BK][BN];

    const int tid = threadIdx.x;
    const int tx = tid & 15;   // 0..15 -> 4 output cols
    const int ty = tid >> 4;   // 0..15 -> 8 output rows
    const int m0 = blockIdx.y * BM;
    const int n0 = blockIdx.x * BN;

    float acc[8][4];
    #pragma unroll
    for (int i = 0; i < 8; i++)
        #pragma unroll
        for (int j = 0; j < 4; j++) acc[i][j] = 0.f;

    const int K2 = 2 * K;
    for (int k0 = 0; k0 < K2; k0 += BK) {
        const bool neigh = (k0 >= K);
        const int kbase = neigh ? (k0 - K) : k0;
        const float* __restrict__ Aptr = neigh ? Agg : Adst;
        const float* __restrict__ Bptr = neigh ? Wn : Ws;

        // A tile: 128 rows x 16 k = 512 float4 loads, 2 per thread
        #pragma unroll
        for (int j = 0; j < 2; j++) {
            int idx = tid + j * 256;       // 0..511
            int r   = idx >> 2;            // tile row 0..127
            int kq  = idx & 3;             // which float4 in the 16-wide k strip
            int grow = m0 + r;
            float4 v = make_float4(0.f, 0.f, 0.f, 0.f);
            if (grow < M) {
                v = reinterpret_cast<const float4*>(Aptr)
                        [((long long)grow * K + kbase) / 4 + kq];
                if (neigh) {
                    float s = invdeg[grow];
                    v.x *= s; v.y *= s; v.z *= s; v.w *= s;
                }
            }
            As[r][kq * 4 + 0] = v.x;
            As[r][kq * 4 + 1] = v.y;
            As[r][kq * 4 + 2] = v.z;
            As[r][kq * 4 + 3] = v.w;
        }

        // B tile: 16 x 64, 4 scalar loads per thread (guards handle N=47)
        {
            int r  = tid >> 4;             // 0..15
            int c4 = (tid & 15) * 4;
            const float* brow = Bptr + (long long)(kbase + r) * N;
            #pragma unroll
            for (int j = 0; j < 4; j++) {
                int n = n0 + c4 + j;
                Bs[r][c4 + j] = (n < N) ? brow[n] : 0.f;
            }
        }
        __syncthreads();

        #pragma unroll
        for (int k = 0; k < BK; k++) {
            float b[4], a[8];
            #pragma unroll
            for (int j = 0; j < 4; j++) b[j] = Bs[k][tx * 4 + j];
            #pragma unroll
            for (int i = 0; i < 8; i++) a[i] = As[ty * 8 + i][k];
            #pragma unroll
            for (int i = 0; i < 8; i++)
                #pragma unroll
                for (int j = 0; j < 4; j++) acc[i][j] += a[i] * b[j];
        }
        __syncthreads();
    }

    // epilogue: bias + optional relu
    #pragma unroll
    for (int i = 0; i < 8; i++) {
        int m = m0 + ty * 8 + i;
        if (m >= M) continue;
        #pragma unroll
        for (int j = 0; j < 4; j++) {
            int n = n0 + tx * 4 + j;
            if (n >= N) continue;
            float v = acc[i][j] + bias[n];
            if (do_relu) v = fmaxf(v, 0.f);
            out[(long long)m * N + n] = v;
        }
    }
}

// ---------------- host orchestration ----------------
static inline int grid_for(long long total_threads, int block) {
    long long g = (total_threads + block - 1) / block;
    if (g > 118784) g = 118784;  // grid-stride covers the rest
    if (g < 1) g = 1;
    return (int)g;
}

extern "C" void kernel_launch(void* const* d_in, const int* in_sizes, int n_in,
                              void* d_out, int out_size) {
    const float* x    = (const float*)d_in[0];
    const int*   src0 = (const int*)  d_in[1];
    const int*   dst0 = (const int*)  d_in[2];
    const int*   src1 = (const int*)  d_in[3];
    const int*   dst1 = (const int*)  d_in[4];
    const int*   src2 = (const int*)  d_in[5];
    const int*   dst2 = (const int*)  d_in[6];
    const float* Ws0  = (const float*)d_in[7];
    const float* Wn0  = (const float*)d_in[8];
    const float* b0   = (const float*)d_in[9];
    const float* Ws1  = (const float*)d_in[10];
    const float* Wn1  = (const float*)d_in[11];
    const float* b1   = (const float*)d_in[12];
    const float* Ws2  = (const float*)d_in[13];
    const float* Wn2  = (const float*)d_in[14];
    const float* b2   = (const float*)d_in[15];
    float* out = (float*)d_out;

    float *agg0, *deg0, *h1, *agg1, *deg1, *h2, *agg2, *deg2;
    cudaGetSymbolAddress((void**)&agg0, g_agg0);
    cudaGetSymbolAddress((void**)&deg0, g_deg0);
    cudaGetSymbolAddress((void**)&h1,   g_h1);
    cudaGetSymbolAddress((void**)&agg1, g_agg1);
    cudaGetSymbolAddress((void**)&deg1, g_deg1);
    cudaGetSymbolAddress((void**)&h2,   g_h2);
    cudaGetSymbolAddress((void**)&agg2, g_agg2);
    cudaGetSymbolAddress((void**)&deg2, g_deg2);

    const int TB = 256;

    // ---- layer 0: x[300000,128] -> h1[100000,256], relu ----
    {
        long long nagg4 = (long long)NDST0 * D_IN / 4;
        fill0_kernel<<<grid_for(nagg4, TB), TB>>>((float4*)agg0, nagg4);
        fill0_kernel<<<grid_for(NDST0 / 4, TB), TB>>>((float4*)deg0, NDST0 / 4);
        long long tot = (long long)NE0 << 5;  // d/4 = 32
        scatter_kernel<<<grid_for(tot, TB), TB>>>(x, src0, dst0, agg0, deg0, NE0, 5);
        invdeg_kernel<<<(NDST0 + TB - 1) / TB, TB>>>(deg0, NDST0);
        dim3 g((D_H + BN - 1) / BN, (NDST0 + BM - 1) / BM);
        sage_gemm_kernel<<<g, TB>>>(x, agg0, deg0, Ws0, Wn0, b0, h1,
                                    NDST0, D_H, D_IN, 1);
    }

    // ---- layer 1: h1[100000,256] -> h2[20000,256], relu ----
    {
        long long nagg4 = (long long)NDST1 * D_H / 4;
        fill0_kernel<<<grid_for(nagg4, TB), TB>>>((float4*)agg1, nagg4);
        fill0_kernel<<<grid_for(NDST1 / 4, TB), TB>>>((float4*)deg1, NDST1 / 4);
        long long tot = (long long)NE1 << 6;  // d/4 = 64
        scatter_kernel<<<grid_for(tot, TB), TB>>>(h1, src1, dst1, agg1, deg1, NE1, 6);
        invdeg_kernel<<<(NDST1 + TB - 1) / TB, TB>>>(deg1, NDST1);
        dim3 g((D_H + BN - 1) / BN, (NDST1 + BM - 1) / BM);
        sage_gemm_kernel<<<g, TB>>>(h1, agg1, deg1, Ws1, Wn1, b1, h2,
                                    NDST1, D_H, D_H, 1);
    }

    // ---- layer 2: h2[20000,256] -> out[4096,47], no relu ----
    {
        long long nagg4 = (long long)NDST2 * D_H / 4;
        fill0_kernel<<<grid_for(nagg4, TB), TB>>>((float4*)agg2, nagg4);
        fill0_kernel<<<grid_for(NDST2 / 4, TB), TB>>>((float4*)deg2, NDST2 / 4);
        long long tot = (long long)NE2 << 6;  // d/4 = 64
        scatter_kernel<<<grid_for(tot, TB), TB>>>(h2, src2, dst2, agg2, deg2, NE2, 6);
        invdeg_kernel<<<(NDST2 + TB - 1) / TB, TB>>>(deg2, NDST2);
        dim3 g((D_OUT + BN - 1) / BN, (NDST2 + BM - 1) / BM);
        sage_gemm_kernel<<<g, TB>>>(h2, agg2, deg2, Ws2, Wn2, b2, out,
                                    NDST2, D_OUT, D_H, 0);
    }
}

// round 5
// speedup vs baseline: 1.6905x; 1.6905x over previous
#include <cuda_runtime.h>
#include <cstdint>

// ---------------- problem constants ----------------
#define NDST0  100000
#define NDST1  20000
#define NDST2  4096
#define NE0    1000000
#define NE1    300000
#define NE2    61440
#define D_IN   128
#define D_H    256
#define D_OUT  47

// ---------------- scratch (device globals: allocation-free) ----------------
__device__ float g_agg0[(size_t)NDST0 * D_IN];
__device__ float g_deg0[NDST0];
__device__ float g_h1[(size_t)NDST0 * D_H];
__device__ float g_agg1[(size_t)NDST1 * D_H];
__device__ float g_deg1[NDST1];
__device__ float g_h2[(size_t)NDST1 * D_H];
__device__ float g_agg2[(size_t)NDST2 * D_H];
__device__ float g_deg2[NDST2];
// transposed/concat weights: Bt[n][k2] = (k2<K ? Ws[k2][n] : Wn[k2-K][n])
__device__ float g_Bt0[(size_t)256 * 256];
__device__ float g_Bt1[(size_t)256 * 512];
__device__ float g_Bt2[(size_t)64 * 512];

// ---------------- helpers ----------------
__device__ __forceinline__ uint32_t smem_u32(const void* p) {
    uint32_t a;
    asm("{ .reg .u64 t; cvta.to.shared.u64 t, %1; cvt.u32.u64 %0, t; }"
        : "=r"(a) : "l"(p));
    return a;
}

__device__ __forceinline__ void cp16(uint32_t dst, const float* src, int sz) {
    asm volatile("cp.async.cg.shared.global [%0], [%1], 16, %2;"
                 :: "r"(dst), "l"(src), "r"(sz));
}

__device__ __forceinline__ uint32_t f2tf32(float f) {
    uint32_t r;
    asm("cvt.rna.tf32.f32 %0, %1;" : "=r"(r) : "f"(f));
    return r;
}

__device__ __forceinline__ void mma_tf32(float* c, const uint32_t* a, const uint32_t* b) {
    asm volatile(
        "mma.sync.aligned.m16n8k8.row.col.f32.tf32.tf32.f32 "
        "{%0,%1,%2,%3}, {%4,%5,%6,%7}, {%8,%9}, {%0,%1,%2,%3};"
        : "+f"(c[0]), "+f"(c[1]), "+f"(c[2]), "+f"(c[3])
        : "r"(a[0]), "r"(a[1]), "r"(a[2]), "r"(a[3]), "r"(b[0]), "r"(b[1]));
}

// ---------------- utility kernels ----------------
__global__ void fill0_kernel(float4* __restrict__ p, long long n4) {
    long long i = (long long)blockIdx.x * blockDim.x + threadIdx.x;
    long long stride = (long long)gridDim.x * blockDim.x;
    float4 z = make_float4(0.f, 0.f, 0.f, 0.f);
    for (; i < n4; i += stride) p[i] = z;
}

// agg[m][*] *= 1/max(deg[m],1)  (folds mean-normalization into the aggregate)
__global__ void scale_agg_kernel(float4* __restrict__ agg, const float* __restrict__ deg,
                                 long long n4, int shift /* log2(d/4) */) {
    long long i = (long long)blockIdx.x * blockDim.x + threadIdx.x;
    long long stride = (long long)gridDim.x * blockDim.x;
    for (; i < n4; i += stride) {
        int m = (int)(i >> shift);
        float s = 1.0f / fmaxf(deg[m], 1.0f);
        float4 v = agg[i];
        v.x *= s; v.y *= s; v.z *= s; v.w *= s;
        agg[i] = v;
    }
}

// Bt[n][k2] = k2<K ? Ws[k2][n] : Wn[k2-K][n], rows n>=N_out zero-padded
__global__ void build_bt_kernel(const float* __restrict__ Ws, const float* __restrict__ Wn,
                                float* __restrict__ Bt, int K, int N_out, int N_pad) {
    int K2 = 2 * K;
    long long total = (long long)N_pad * K2;
    long long i = (long long)blockIdx.x * blockDim.x + threadIdx.x;
    if (i >= total) return;
    int n = (int)(i / K2);
    int k2 = (int)(i % K2);
    float v = 0.f;
    if (n < N_out)
        v = (k2 < K) ? Ws[(size_t)k2 * N_out + n] : Wn[(size_t)(k2 - K) * N_out + n];
    Bt[i] = v;
}

// ---------------- edge scatter (R1-proven) ----------------
__global__ void scatter_kernel(const float* __restrict__ feat,
                               const int* __restrict__ src,
                               const int* __restrict__ dst,
                               float* __restrict__ agg,
                               float* __restrict__ deg,
                               int E, int shift /* log2(d/4) */) {
    const int d4 = 1 << shift;
    const long long total = (long long)E << shift;
    const long long stride = (long long)gridDim.x * blockDim.x;
    for (long long i = (long long)blockIdx.x * blockDim.x + threadIdx.x;
         i < total; i += stride) {
        int e = (int)(i >> shift);
        int c = (int)(i & (d4 - 1));
        int s  = src[e];
        int dt = dst[e];
        float4 v = reinterpret_cast<const float4*>(feat)[(long long)s * d4 + c];
        float* p = agg + (((long long)dt << shift) + c) * 4;
        asm volatile("red.global.add.v4.f32 [%0], {%1,%2,%3,%4};"
                     :: "l"(p), "f"(v.x), "f"(v.y), "f"(v.z), "f"(v.w)
                     : "memory");
        if (c == 0) atomicAdd(deg + dt, 1.0f);
    }
}

// ---------------- mma.sync tf32 fused SAGE GEMM ----------------
// Per CTA: 128 x NPAD output tile, full N in one tile (A read exactly once).
// K' = 2K concat (dst-half then neighbor-half), chunks of 32 k's,
// double-buffered via cp.async.cg. 8 warps in 2(m) x 4(n) grid; each warp
// computes 64 x NPAD/4 via m16n8k8 tf32 fragments (conflict-free stride-36 smem).
#define LDS_P 36   // padded row stride in floats (144B: 16B-aligned, bank-clean)

template<int NPAD>
__global__ __launch_bounds__(256, 1) void sage_gemm_mma(
    const float* __restrict__ Adst, const float* __restrict__ Agg,
    const float* __restrict__ Bt, const float* __restrict__ bias,
    float* __restrict__ out, int M, int K, int N_out, int relu)
{
    constexpr int NT = NPAD / 32;               // n mma-tiles per warp
    extern __shared__ float smem[];
    float* AsBase = smem;                       // [2][128][LDS_P]
    float* BsBase = smem + 2 * 128 * LDS_P;     // [2][NPAD][LDS_P]

    const uint32_t sb = smem_u32(smem);
    const uint32_t sb_b = sb + 2u * 128u * LDS_P * 4u;
    const int tid = threadIdx.x;
    const int wid = tid >> 5, lane = tid & 31;
    const int g = lane >> 2, tg = lane & 3;
    const int wm = wid & 1, wn = wid >> 1;      // 2 x 4 warp grid
    const int m0 = blockIdx.x * 128;
    const int K2 = 2 * K;
    const int nc = K2 / 32;

    float acc[4][NT][4];
    #pragma unroll
    for (int m = 0; m < 4; m++)
        #pragma unroll
        for (int n = 0; n < NT; n++)
            #pragma unroll
            for (int j = 0; j < 4; j++) acc[m][n][j] = 0.f;

    auto issue = [&](int ic) {
        const int buf = ic & 1;
        const int kb_b = ic * 32;
        int kb = kb_b;
        const float* __restrict__ Ap = Adst;
        if (kb >= K) { Ap = Agg; kb -= K; }
        // A chunk: 128 rows x 8 float4
        #pragma unroll
        for (int t = 0; t < 4; t++) {
            int idx = tid + t * 256;
            int r = idx >> 3, q = idx & 7;
            int gr = m0 + r;
            int grc = gr < M ? gr : (M - 1);
            const float* src = Ap + (size_t)grc * K + kb + q * 4;
            uint32_t dst = sb + (uint32_t)((buf * 128 + r) * LDS_P + q * 4) * 4u;
            cp16(dst, src, gr < M ? 16 : 0);
        }
        // B chunk: NPAD rows x 8 float4
        #pragma unroll
        for (int t = 0; t < NPAD / 32; t++) {
            int idx = tid + t * 256;
            int n = idx >> 3, q = idx & 7;
            const float* src = Bt + (size_t)n * K2 + kb_b + q * 4;
            uint32_t dst = sb_b + (uint32_t)((buf * NPAD + n) * LDS_P + q * 4) * 4u;
            cp16(dst, src, 16);
        }
        asm volatile("cp.async.commit_group;" ::: "memory");
    };

    issue(0);
    for (int ic = 0; ic < nc; ic++) {
        if (ic + 1 < nc) {
            issue(ic + 1);
            asm volatile("cp.async.wait_group 1;" ::: "memory");
        } else {
            asm volatile("cp.async.wait_group 0;" ::: "memory");
        }
        __syncthreads();

        const float* a_ = AsBase + (ic & 1) * 128 * LDS_P;
        const float* b_ = BsBase + (ic & 1) * NPAD * LDS_P;

        #pragma unroll
        for (int s = 0; s < 4; s++) {
            const int c = s * 8 + tg;
            uint32_t af[4][4];
            #pragma unroll
            for (int m = 0; m < 4; m++) {
                int r = wm * 64 + m * 16 + g;
                af[m][0] = f2tf32(a_[r * LDS_P + c]);
                af[m][1] = f2tf32(a_[(r + 8) * LDS_P + c]);
                af[m][2] = f2tf32(a_[r * LDS_P + c + 4]);
                af[m][3] = f2tf32(a_[(r + 8) * LDS_P + c + 4]);
            }
            uint32_t bf[NT][2];
            #pragma unroll
            for (int n = 0; n < NT; n++) {
                int nn = wn * (NPAD / 4) + n * 8 + g;
                bf[n][0] = f2tf32(b_[nn * LDS_P + c]);
                bf[n][1] = f2tf32(b_[nn * LDS_P + c + 4]);
            }
            #pragma unroll
            for (int m = 0; m < 4; m++)
                #pragma unroll
                for (int n = 0; n < NT; n++)
                    mma_tf32(acc[m][n], af[m], bf[n]);
        }
        __syncthreads();
    }

    // epilogue: bias + optional relu, scalar stores with guards
    #pragma unroll
    for (int m = 0; m < 4; m++) {
        const int r0 = m0 + wm * 64 + m * 16 + g;
        #pragma unroll
        for (int n = 0; n < NT; n++) {
            const int c0 = wn * (NPAD / 4) + n * 8 + tg * 2;
            #pragma unroll
            for (int i = 0; i < 2; i++) {
                const int r = r0 + i * 8;
                if (r >= M) continue;
                #pragma unroll
                for (int j = 0; j < 2; j++) {
                    const int cc = c0 + j;
                    if (cc >= N_out) continue;
                    float v = acc[m][n][i * 2 + j] + bias[cc];
                    if (relu) v = fmaxf(v, 0.f);
                    out[(size_t)r * N_out + cc] = v;
                }
            }
        }
    }
}

#define SMEM256 ((2 * 128 * LDS_P + 2 * 256 * LDS_P) * 4)   // 110592
#define SMEM64  ((2 * 128 * LDS_P + 2 * 64 * LDS_P) * 4)    // 55296

// ---------------- host orchestration ----------------
static inline int grid_for(long long total_threads, int block) {
    long long g = (total_threads + block - 1) / block;
    if (g > 118784) g = 118784;
    if (g < 1) g = 1;
    return (int)g;
}

extern "C" void kernel_launch(void* const* d_in, const int* in_sizes, int n_in,
                              void* d_out, int out_size) {
    const float* x    = (const float*)d_in[0];
    const int*   src0 = (const int*)  d_in[1];
    const int*   dst0 = (const int*)  d_in[2];
    const int*   src1 = (const int*)  d_in[3];
    const int*   dst1 = (const int*)  d_in[4];
    const int*   src2 = (const int*)  d_in[5];
    const int*   dst2 = (const int*)  d_in[6];
    const float* Ws0  = (const float*)d_in[7];
    const float* Wn0  = (const float*)d_in[8];
    const float* b0   = (const float*)d_in[9];
    const float* Ws1  = (const float*)d_in[10];
    const float* Wn1  = (const float*)d_in[11];
    const float* b1   = (const float*)d_in[12];
    const float* Ws2  = (const float*)d_in[13];
    const float* Wn2  = (const float*)d_in[14];
    const float* b2   = (const float*)d_in[15];
    float* out = (float*)d_out;

    float *agg0, *deg0, *h1, *agg1, *deg1, *h2, *agg2, *deg2, *bt0, *bt1, *bt2;
    cudaGetSymbolAddress((void**)&agg0, g_agg0);
    cudaGetSymbolAddress((void**)&deg0, g_deg0);
    cudaGetSymbolAddress((void**)&h1,   g_h1);
    cudaGetSymbolAddress((void**)&agg1, g_agg1);
    cudaGetSymbolAddress((void**)&deg1, g_deg1);
    cudaGetSymbolAddress((void**)&h2,   g_h2);
    cudaGetSymbolAddress((void**)&agg2, g_agg2);
    cudaGetSymbolAddress((void**)&deg2, g_deg2);
    cudaGetSymbolAddress((void**)&bt0,  g_Bt0);
    cudaGetSymbolAddress((void**)&bt1,  g_Bt1);
    cudaGetSymbolAddress((void**)&bt2,  g_Bt2);

    cudaFuncSetAttribute(sage_gemm_mma<256>,
                         cudaFuncAttributeMaxDynamicSharedMemorySize, SMEM256);
    cudaFuncSetAttribute(sage_gemm_mma<64>,
                         cudaFuncAttributeMaxDynamicSharedMemorySize, SMEM64);

    const int TB = 256;

    // weight transposes (tiny, once per launch)
    build_bt_kernel<<<(256 * 256 + TB - 1) / TB, TB>>>(Ws0, Wn0, bt0, 128, 256, 256);
    build_bt_kernel<<<(256 * 512 + TB - 1) / TB, TB>>>(Ws1, Wn1, bt1, 256, 256, 256);
    build_bt_kernel<<<(64 * 512 + TB - 1) / TB, TB>>>(Ws2, Wn2, bt2, 256, 47, 64);

    // ---- layer 0: x[300000,128] -> h1[100000,256], relu ----
    {
        long long nagg4 = (long long)NDST0 * D_IN / 4;
        fill0_kernel<<<grid_for(nagg4, TB), TB>>>((float4*)agg0, nagg4);
        fill0_kernel<<<grid_for(NDST0 / 4, TB), TB>>>((float4*)deg0, NDST0 / 4);
        scatter_kernel<<<grid_for((long long)NE0 << 5, TB), TB>>>(x, src0, dst0,
                                                                  agg0, deg0, NE0, 5);
        scale_agg_kernel<<<grid_for(nagg4, TB), TB>>>((float4*)agg0, deg0, nagg4, 5);
        sage_gemm_mma<256><<<(NDST0 + 127) / 128, 256, SMEM256>>>(
            x, agg0, bt0, b0, h1, NDST0, D_IN, 256, 1);
    }

    // ---- layer 1: h1[100000,256] -> h2[20000,256], relu ----
    {
        long long nagg4 = (long long)NDST1 * D_H / 4;
        fill0_kernel<<<grid_for(nagg4, TB), TB>>>((float4*)agg1, nagg4);
        fill0_kernel<<<grid_for(NDST1 / 4, TB), TB>>>((float4*)deg1, NDST1 / 4);
        scatter_kernel<<<grid_for((long long)NE1 << 6, TB), TB>>>(h1, src1, dst1,
                                                                  agg1, deg1, NE1, 6);
        scale_agg_kernel<<<grid_for(nagg4, TB), TB>>>((float4*)agg1, deg1, nagg4, 6);
        sage_gemm_mma<256><<<(NDST1 + 127) / 128, 256, SMEM256>>>(
            h1, agg1, bt1, b1, h2, NDST1, D_H, 256, 1);
    }

    // ---- layer 2: h2[20000,256] -> out[4096,47], no relu ----
    {
        long long nagg4 = (long long)NDST2 * D_H / 4;
        fill0_kernel<<<grid_for(nagg4, TB), TB>>>((float4*)agg2, nagg4);
        fill0_kernel<<<grid_for(NDST2 / 4, TB), TB>>>((float4*)deg2, NDST2 / 4);
        scatter_kernel<<<grid_for((long long)NE2 << 6, TB), TB>>>(h2, src2, dst2,
                                                                  agg2, deg2, NE2, 6);
        scale_agg_kernel<<<grid_for(nagg4, TB), TB>>>((float4*)agg2, deg2, nagg4, 6);
        sage_gemm_mma<64><<<(NDST2 + 127) / 128, 256, SMEM64>>>(
            h2, agg2, bt2, b2, out, NDST2, D_H, 47, 0);
    }
}

// round 6
// speedup vs baseline: 2.6546x; 1.5703x over previous
#include <cuda_runtime.h>
#include <cstdint>

// ---------------- problem constants ----------------
#define NDST0  100000
#define NDST1  20000
#define NDST2  4096
#define NE0    1000000
#define NE1    300000
#define NE2    61440
#define D_IN   128
#define D_H    256
#define D_OUT  47

// ---------------- scratch (device globals: allocation-free) ----------------
__device__ float g_agg0[(size_t)NDST0 * D_IN];
__device__ float g_h1[(size_t)NDST0 * D_H];
__device__ float g_agg1[(size_t)NDST1 * D_H];
__device__ float g_h2[(size_t)NDST1 * D_H];
__device__ float g_agg2[(size_t)NDST2 * D_H];
// CSR scratch (sized for the largest layer)
__device__ int g_cnt[NDST0];
__device__ int g_rowptr[NDST0 + 1];
__device__ int g_cur[NDST0];
__device__ int g_eidx[NE0];
__device__ int g_bsum[512];
// transposed/concat weights: Bt[n][k2] = (k2<K ? Ws[k2][n] : Wn[k2-K][n])
__device__ float g_Bt0[(size_t)256 * 256];
__device__ float g_Bt1[(size_t)256 * 512];
__device__ float g_Bt2[(size_t)64 * 512];

// ---------------- helpers ----------------
__device__ __forceinline__ uint32_t smem_u32(const void* p) {
    uint32_t a;
    asm("{ .reg .u64 t; cvta.to.shared.u64 t, %1; cvt.u32.u64 %0, t; }"
        : "=r"(a) : "l"(p));
    return a;
}

__device__ __forceinline__ void cp16(uint32_t dst, const float* src, int sz) {
    asm volatile("cp.async.cg.shared.global [%0], [%1], 16, %2;"
                 :: "r"(dst), "l"(src), "r"(sz));
}

__device__ __forceinline__ uint32_t f2tf32(float f) {
    uint32_t r;
    asm("cvt.rna.tf32.f32 %0, %1;" : "=r"(r) : "f"(f));
    return r;
}

__device__ __forceinline__ void mma_tf32(float* c, const uint32_t* a, const uint32_t* b) {
    asm volatile(
        "mma.sync.aligned.m16n8k8.row.col.f32.tf32.tf32.f32 "
        "{%0,%1,%2,%3}, {%4,%5,%6,%7}, {%8,%9}, {%0,%1,%2,%3};"
        : "+f"(c[0]), "+f"(c[1]), "+f"(c[2]), "+f"(c[3])
        : "r"(a[0]), "r"(a[1]), "r"(a[2]), "r"(a[3]), "r"(b[0]), "r"(b[1]));
}

// ---------------- CSR build kernels ----------------
__global__ void zero_int_kernel(int* __restrict__ p, int n) {
    int i = blockIdx.x * blockDim.x + threadIdx.x;
    if (i < n) p[i] = 0;
}

__global__ void hist_kernel(const int* __restrict__ dst, int* __restrict__ cnt, int E) {
    int i = blockIdx.x * blockDim.x + threadIdx.x;
    if (i < E) atomicAdd(&cnt[dst[i]], 1);
}

// per-256-block sums of cnt
__global__ void scan1_kernel(const int* __restrict__ cnt, int* __restrict__ bsum, int n) {
    __shared__ int s[8];
    int i = blockIdx.x * 256 + threadIdx.x;
    int v = (i < n) ? cnt[i] : 0;
    #pragma unroll
    for (int o = 16; o; o >>= 1) v += __shfl_down_sync(~0u, v, o);
    if ((threadIdx.x & 31) == 0) s[threadIdx.x >> 5] = v;
    __syncthreads();
    if (threadIdx.x < 8) {
        int x = s[threadIdx.x];
        #pragma unroll
        for (int o = 4; o; o >>= 1) x += __shfl_down_sync(0xff, x, o);
        if (threadIdx.x == 0) bsum[blockIdx.x] = x;
    }
}

// single-block exclusive scan of block sums (nb <= 512)
__global__ void scan2_kernel(int* __restrict__ bsum, int nb) {
    __shared__ int s[512];
    int t = threadIdx.x;
    int v = (t < nb) ? bsum[t] : 0;
    s[t] = v;
    __syncthreads();
    for (int o = 1; o < 512; o <<= 1) {
        int u = (t >= o) ? s[t - o] : 0;
        __syncthreads();
        s[t] += u;
        __syncthreads();
    }
    if (t < nb) bsum[t] = s[t] - v;   // exclusive
}

// per-block exclusive scan + offset -> rowptr, cur
__global__ void scan3_kernel(const int* __restrict__ cnt, const int* __restrict__ bsum,
                             int* __restrict__ rowptr, int* __restrict__ cur,
                             int n, int E) {
    __shared__ int s[256];
    int t = threadIdx.x;
    int i = blockIdx.x * 256 + t;
    int v = (i < n) ? cnt[i] : 0;
    s[t] = v;
    __syncthreads();
    for (int o = 1; o < 256; o <<= 1) {
        int u = (t >= o) ? s[t - o] : 0;
        __syncthreads();
        s[t] += u;
        __syncthreads();
    }
    int ex = s[t] - v + bsum[blockIdx.x];
    if (i < n) { rowptr[i] = ex; cur[i] = ex; }
    if (i == 0) rowptr[n] = E;
}

__global__ void fillidx_kernel(const int* __restrict__ src, const int* __restrict__ dst,
                               int* __restrict__ cur, int* __restrict__ eidx, int E) {
    int i = blockIdx.x * blockDim.x + threadIdx.x;
    if (i < E) {
        int p = atomicAdd(&cur[dst[i]], 1);
        eidx[p] = src[i];
    }
}

// ---------------- gather aggregation: one warp per dst row ----------------
// agg[w][:] = mean of feat[eidx[j]][:] over j in [rowptr[w], rowptr[w+1]).
// V = d/128 (float4 chunks per lane). No atomics, no fill, mean folded in.
template<int V>
__global__ __launch_bounds__(256) void gather_agg_kernel(
    const float4* __restrict__ feat, const int* __restrict__ rowptr,
    const int* __restrict__ eidx, float4* __restrict__ agg, int n_dst)
{
    int w = (blockIdx.x * blockDim.x + threadIdx.x) >> 5;
    if (w >= n_dst) return;
    int lane = threadIdx.x & 31;
    int beg = rowptr[w], end = rowptr[w + 1];

    float4 acc[V];
    #pragma unroll
    for (int v = 0; v < V; v++) acc[v] = make_float4(0.f, 0.f, 0.f, 0.f);

    int j = beg;
    for (; j + 1 < end; j += 2) {
        int s0 = eidx[j], s1 = eidx[j + 1];
        #pragma unroll
        for (int v = 0; v < V; v++) {
            float4 f0 = feat[(size_t)s0 * (32 * V) + v * 32 + lane];
            float4 f1 = feat[(size_t)s1 * (32 * V) + v * 32 + lane];
            acc[v].x += f0.x + f1.x;
            acc[v].y += f0.y + f1.y;
            acc[v].z += f0.z + f1.z;
            acc[v].w += f0.w + f1.w;
        }
    }
    if (j < end) {
        int s0 = eidx[j];
        #pragma unroll
        for (int v = 0; v < V; v++) {
            float4 f0 = feat[(size_t)s0 * (32 * V) + v * 32 + lane];
            acc[v].x += f0.x; acc[v].y += f0.y; acc[v].z += f0.z; acc[v].w += f0.w;
        }
    }

    float inv = 1.0f / (float)max(end - beg, 1);
    #pragma unroll
    for (int v = 0; v < V; v++) {
        float4 o;
        o.x = acc[v].x * inv; o.y = acc[v].y * inv;
        o.z = acc[v].z * inv; o.w = acc[v].w * inv;
        agg[(size_t)w * (32 * V) + v * 32 + lane] = o;
    }
}

// ---------------- Bt build ----------------
__global__ void build_bt_kernel(const float* __restrict__ Ws, const float* __restrict__ Wn,
                                float* __restrict__ Bt, int K, int N_out, int N_pad) {
    int K2 = 2 * K;
    long long total = (long long)N_pad * K2;
    long long i = (long long)blockIdx.x * blockDim.x + threadIdx.x;
    if (i >= total) return;
    int n = (int)(i / K2);
    int k2 = (int)(i % K2);
    float v = 0.f;
    if (n < N_out)
        v = (k2 < K) ? Ws[(size_t)k2 * N_out + n] : Wn[(size_t)(k2 - K) * N_out + n];
    Bt[i] = v;
}

// ---------------- mma.sync tf32 fused SAGE GEMM (R5-proven) ----------------
#define LDS_P 36

template<int NPAD>
__global__ __launch_bounds__(256, 1) void sage_gemm_mma(
    const float* __restrict__ Adst, const float* __restrict__ Agg,
    const float* __restrict__ Bt, const float* __restrict__ bias,
    float* __restrict__ out, int M, int K, int N_out, int relu)
{
    constexpr int NT = NPAD / 32;
    extern __shared__ float smem[];
    float* AsBase = smem;
    float* BsBase = smem + 2 * 128 * LDS_P;

    const uint32_t sb = smem_u32(smem);
    const uint32_t sb_b = sb + 2u * 128u * LDS_P * 4u;
    const int tid = threadIdx.x;
    const int wid = tid >> 5, lane = tid & 31;
    const int g = lane >> 2, tg = lane & 3;
    const int wm = wid & 1, wn = wid >> 1;
    const int m0 = blockIdx.x * 128;
    const int K2 = 2 * K;
    const int nc = K2 / 32;

    float acc[4][NT][4];
    #pragma unroll
    for (int m = 0; m < 4; m++)
        #pragma unroll
        for (int n = 0; n < NT; n++)
            #pragma unroll
            for (int j = 0; j < 4; j++) acc[m][n][j] = 0.f;

    auto issue = [&](int ic) {
        const int buf = ic & 1;
        const int kb_b = ic * 32;
        int kb = kb_b;
        const float* __restrict__ Ap = Adst;
        if (kb >= K) { Ap = Agg; kb -= K; }
        #pragma unroll
        for (int t = 0; t < 4; t++) {
            int idx = tid + t * 256;
            int r = idx >> 3, q = idx & 7;
            int gr = m0 + r;
            int grc = gr < M ? gr : (M - 1);
            const float* src = Ap + (size_t)grc * K + kb + q * 4;
            uint32_t dst = sb + (uint32_t)((buf * 128 + r) * LDS_P + q * 4) * 4u;
            cp16(dst, src, gr < M ? 16 : 0);
        }
        #pragma unroll
        for (int t = 0; t < NPAD / 32; t++) {
            int idx = tid + t * 256;
            int n = idx >> 3, q = idx & 7;
            const float* src = Bt + (size_t)n * K2 + kb_b + q * 4;
            uint32_t dst = sb_b + (uint32_t)((buf * NPAD + n) * LDS_P + q * 4) * 4u;
            cp16(dst, src, 16);
        }
        asm volatile("cp.async.commit_group;" ::: "memory");
    };

    issue(0);
    for (int ic = 0; ic < nc; ic++) {
        if (ic + 1 < nc) {
            issue(ic + 1);
            asm volatile("cp.async.wait_group 1;" ::: "memory");
        } else {
            asm volatile("cp.async.wait_group 0;" ::: "memory");
        }
        __syncthreads();

        const float* a_ = AsBase + (ic & 1) * 128 * LDS_P;
        const float* b_ = BsBase + (ic & 1) * NPAD * LDS_P;

        #pragma unroll
        for (int s = 0; s < 4; s++) {
            const int c = s * 8 + tg;
            uint32_t af[4][4];
            #pragma unroll
            for (int m = 0; m < 4; m++) {
                int r = wm * 64 + m * 16 + g;
                af[m][0] = f2tf32(a_[r * LDS_P + c]);
                af[m][1] = f2tf32(a_[(r + 8) * LDS_P + c]);
                af[m][2] = f2tf32(a_[r * LDS_P + c + 4]);
                af[m][3] = f2tf32(a_[(r + 8) * LDS_P + c + 4]);
            }
            uint32_t bf[NT][2];
            #pragma unroll
            for (int n = 0; n < NT; n++) {
                int nn = wn * (NPAD / 4) + n * 8 + g;
                bf[n][0] = f2tf32(b_[nn * LDS_P + c]);
                bf[n][1] = f2tf32(b_[nn * LDS_P + c + 4]);
            }
            #pragma unroll
            for (int m = 0; m < 4; m++)
                #pragma unroll
                for (int n = 0; n < NT; n++)
                    mma_tf32(acc[m][n], af[m], bf[n]);
        }
        __syncthreads();
    }

    #pragma unroll
    for (int m = 0; m < 4; m++) {
        const int r0 = m0 + wm * 64 + m * 16 + g;
        #pragma unroll
        for (int n = 0; n < NT; n++) {
            const int c0 = wn * (NPAD / 4) + n * 8 + tg * 2;
            #pragma unroll
            for (int i = 0; i < 2; i++) {
                const int r = r0 + i * 8;
                if (r >= M) continue;
                #pragma unroll
                for (int j = 0; j < 2; j++) {
                    const int cc = c0 + j;
                    if (cc >= N_out) continue;
                    float v = acc[m][n][i * 2 + j] + bias[cc];
                    if (relu) v = fmaxf(v, 0.f);
                    out[(size_t)r * N_out + cc] = v;
                }
            }
        }
    }
}

#define SMEM256 ((2 * 128 * LDS_P + 2 * 256 * LDS_P) * 4)
#define SMEM64  ((2 * 128 * LDS_P + 2 * 64 * LDS_P) * 4)

// ---------------- host orchestration ----------------
extern "C" void kernel_launch(void* const* d_in, const int* in_sizes, int n_in,
                              void* d_out, int out_size) {
    const float* x    = (const float*)d_in[0];
    const int*   src0 = (const int*)  d_in[1];
    const int*   dst0 = (const int*)  d_in[2];
    const int*   src1 = (const int*)  d_in[3];
    const int*   dst1 = (const int*)  d_in[4];
    const int*   src2 = (const int*)  d_in[5];
    const int*   dst2 = (const int*)  d_in[6];
    const float* Ws0  = (const float*)d_in[7];
    const float* Wn0  = (const float*)d_in[8];
    const float* b0   = (const float*)d_in[9];
    const float* Ws1  = (const float*)d_in[10];
    const float* Wn1  = (const float*)d_in[11];
    const float* b1   = (const float*)d_in[12];
    const float* Ws2  = (const float*)d_in[13];
    const float* Wn2  = (const float*)d_in[14];
    const float* b2   = (const float*)d_in[15];
    float* out = (float*)d_out;

    float *agg0, *h1, *agg1, *h2, *agg2, *bt0, *bt1, *bt2;
    int *cnt, *rowptr, *cur, *eidx, *bsum;
    cudaGetSymbolAddress((void**)&agg0, g_agg0);
    cudaGetSymbolAddress((void**)&h1,   g_h1);
    cudaGetSymbolAddress((void**)&agg1, g_agg1);
    cudaGetSymbolAddress((void**)&h2,   g_h2);
    cudaGetSymbolAddress((void**)&agg2, g_agg2);
    cudaGetSymbolAddress((void**)&cnt,    g_cnt);
    cudaGetSymbolAddress((void**)&rowptr, g_rowptr);
    cudaGetSymbolAddress((void**)&cur,    g_cur);
    cudaGetSymbolAddress((void**)&eidx,   g_eidx);
    cudaGetSymbolAddress((void**)&bsum,   g_bsum);
    cudaGetSymbolAddress((void**)&bt0,  g_Bt0);
    cudaGetSymbolAddress((void**)&bt1,  g_Bt1);
    cudaGetSymbolAddress((void**)&bt2,  g_Bt2);

    cudaFuncSetAttribute(sage_gemm_mma<256>,
                         cudaFuncAttributeMaxDynamicSharedMemorySize, SMEM256);
    cudaFuncSetAttribute(sage_gemm_mma<64>,
                         cudaFuncAttributeMaxDynamicSharedMemorySize, SMEM64);

    const int TB = 256;

    // weight transposes (tiny, once per launch)
    build_bt_kernel<<<(256 * 256 + TB - 1) / TB, TB>>>(Ws0, Wn0, bt0, 128, 256, 256);
    build_bt_kernel<<<(256 * 512 + TB - 1) / TB, TB>>>(Ws1, Wn1, bt1, 256, 256, 256);
    build_bt_kernel<<<(64 * 512 + TB - 1) / TB, TB>>>(Ws2, Wn2, bt2, 256, 47, 64);

    // CSR build + gather aggregation + GEMM per layer
    auto run_csr = [&](const int* src, const int* dst, int E, int n_dst) {
        int nb = (n_dst + 255) / 256;
        zero_int_kernel<<<nb, TB>>>(cnt, n_dst);
        hist_kernel<<<(E + TB - 1) / TB, TB>>>(dst, cnt, E);
        scan1_kernel<<<nb, TB>>>(cnt, bsum, n_dst);
        scan2_kernel<<<1, 512>>>(bsum, nb);
        scan3_kernel<<<nb, TB>>>(cnt, bsum, rowptr, cur, n_dst, E);
        fillidx_kernel<<<(E + TB - 1) / TB, TB>>>(src, dst, cur, eidx, E);
    };

    // ---- layer 0: x[300000,128] -> h1[100000,256], relu ----
    run_csr(src0, dst0, NE0, NDST0);
    gather_agg_kernel<1><<<(NDST0 * 32 + TB - 1) / TB, TB>>>(
        (const float4*)x, rowptr, eidx, (float4*)agg0, NDST0);
    sage_gemm_mma<256><<<(NDST0 + 127) / 128, 256, SMEM256>>>(
        x, agg0, bt0, b0, h1, NDST0, D_IN, 256, 1);

    // ---- layer 1: h1[100000,256] -> h2[20000,256], relu ----
    run_csr(src1, dst1, NE1, NDST1);
    gather_agg_kernel<2><<<(NDST1 * 32 + TB - 1) / TB, TB>>>(
        (const float4*)h1, rowptr, eidx, (float4*)agg1, NDST1);
    sage_gemm_mma<256><<<(NDST1 + 127) / 128, 256, SMEM256>>>(
        h1, agg1, bt1, b1, h2, NDST1, D_H, 256, 1);

    // ---- layer 2: h2[20000,256] -> out[4096,47], no relu ----
    run_csr(src2, dst2, NE2, NDST2);
    gather_agg_kernel<2><<<(NDST2 * 32 + TB - 1) / TB, TB>>>(
        (const float4*)h2, rowptr, eidx, (float4*)agg2, NDST2);
    sage_gemm_mma<64><<<(NDST2 + 127) / 128, 256, SMEM64>>>(
        h2, agg2, bt2, b2, out, NDST2, D_H, 47, 0);
}